// round 7
// baseline (speedup 1.0000x reference)
#include <cuda_runtime.h>
#include <math.h>
#include <stdint.h>

// ---------------- problem constants ----------------
#define NT 20000
#define NC 200000
#define NF 40000
#define E_HC 200000
#define E_BT 200000
#define E_IS 80000
#define E_PT 80000
#define FH 256

// ---------------- scratch offsets (floats) ----------------
static constexpr size_t OFF_FEAT_T = 0;
static constexpr size_t OFF_FEAT_C = OFF_FEAT_T + (size_t)NT * 256;
static constexpr size_t OFF_FEAT_F = OFF_FEAT_C + (size_t)NC * 256;
static constexpr size_t OFF_XCT    = OFF_FEAT_F + (size_t)NF * 256;   // NT x 512
static constexpr size_t OFF_XCC    = OFF_XCT + (size_t)NT * 512;      // NC x 1024
static constexpr size_t OFF_XCF    = OFF_XCC + (size_t)NC * 1024;     // NF x 512
static constexpr size_t OFF_OC1    = OFF_XCF + (size_t)NF * 512;
static constexpr size_t OFF_OT     = OFF_OC1 + (size_t)NC * 256;
static constexpr size_t OFF_OF     = OFF_OT  + (size_t)NT * 256;
static constexpr size_t OFF_OC2    = OFF_OF  + (size_t)NF * 256;
static constexpr size_t OFF_LOGIT  = OFF_OC2 + (size_t)NC * 256;      // 560000*4
static constexpr size_t OFF_SEG    = OFF_LOGIT + 2240000;             // 3,680,000
static constexpr size_t OFF_RLIN   = OFF_SEG + 3680000;               // 49152
static constexpr size_t OFF_ROUT   = OFF_RLIN + 49152;                // 196608
static constexpr size_t OFF_CAT0   = OFF_ROUT + 196608;               // 64*2048
static constexpr size_t OFF_CAT1   = OFF_CAT0 + 131072;               // 256*2048
static constexpr size_t SCRATCH_TOTAL = OFF_CAT1 + 524288;

__device__ float g_scratch[SCRATCH_TOTAL];

// ---------------- PTX helpers ----------------
__device__ __forceinline__ void cp_async16(void* dst, const void* src)
{
    uint32_t d = (uint32_t)__cvta_generic_to_shared(dst);
    asm volatile("cp.async.cg.shared.global [%0], [%1], 16;\n" :: "r"(d), "l"(src));
}
__device__ __forceinline__ void cp_commit() { asm volatile("cp.async.commit_group;\n" ::: "memory"); }
__device__ __forceinline__ void cp_wait0()  { asm volatile("cp.async.wait_group 0;\n" ::: "memory"); }
__device__ __forceinline__ void cp_wait1()  { asm volatile("cp.async.wait_group 1;\n" ::: "memory"); }

__device__ __forceinline__ uint32_t cvt_tf32(float x)
{
    uint32_t r; asm("cvt.rna.tf32.f32 %0, %1;" : "=r"(r) : "f"(x)); return r;
}
__device__ __forceinline__ float round_tf32(float x) { return __uint_as_float(cvt_tf32(x)); }

__device__ __forceinline__ void mma_tf32(float* c, const uint32_t* a, const uint32_t* b)
{
    asm volatile("mma.sync.aligned.m16n8k8.row.col.f32.tf32.tf32.f32 "
                 "{%0,%1,%2,%3}, {%4,%5,%6,%7}, {%8,%9}, {%0,%1,%2,%3};"
                 : "+f"(c[0]), "+f"(c[1]), "+f"(c[2]), "+f"(c[3])
                 : "r"(a[0]), "r"(a[1]), "r"(a[2]), "r"(a[3]), "r"(b[0]), "r"(b[1]));
}

__device__ __forceinline__ uint32_t fmax_key(float f)
{
    int i = __float_as_int(f);
    return (i >= 0) ? ((uint32_t)i | 0x80000000u) : ~(uint32_t)i;
}
__device__ __forceinline__ float fmax_unkey(uint32_t u)
{
    return (u & 0x80000000u) ? __int_as_float((int)(u & 0x7fffffffu))
                             : __int_as_float((int)~u);
}

// ---------------- grouped tf32 GEMM ----------------
struct GemmGroups {
    const float* A[3]; const float* B[3]; const float* bias[3]; float* C[3];
    int M[3]; int N[3];
    int maskX[3]; int shiftX[3];   // tilesX = maskX+1 (power of 2)
    int blockStart[3];             // starts of groups 0,1,2
    int K;
};

template<int CVT_A, int ACT, int ROUND_OUT, int BN, int WARPS_M, int WARPS_N>
__global__ void __launch_bounds__(256, 2)
gemm_grouped(GemmGroups gg)
{
    constexpr int BM = 128, BK = 32;
    constexpr int BKP = 36;
    constexpr int BNP = BN + 8;
    constexpr int WM = BM / WARPS_M, WN = BN / WARPS_N;
    constexpr int MI = WM / 16, NI = WN / 8;
    constexpr int A_STAGE = BM * BKP;
    constexpr int B_STAGE = BK * BNP;
    constexpr int STAGES = 3;

    extern __shared__ float sm[];
    float* Asm = sm;
    float* Bsm = sm + STAGES * A_STAGE;

    const int bid = blockIdx.x;
    const int g = (bid >= gg.blockStart[1]) + (bid >= gg.blockStart[2]);
    const int local = bid - gg.blockStart[g];
    const int tileX = local & gg.maskX[g];
    const int tileY = local >> gg.shiftX[g];

    const float* __restrict__ A = gg.A[g];
    const float* __restrict__ B = gg.B[g];
    const float* __restrict__ bias = gg.bias[g];
    float* __restrict__ C = gg.C[g];
    const int M = gg.M[g], N = gg.N[g], K = gg.K;
    const int rowBase = tileY * BM;
    const int colBase = tileX * BN;

    const int tid  = threadIdx.x;
    const int lane = tid & 31;
    const int warp = tid >> 5;
    const int gq   = lane >> 2;
    const int tig  = lane & 3;
    const int warpM = warp % WARPS_M;
    const int warpN = warp / WARPS_M;

    float acc[MI][NI][4];
#pragma unroll
    for (int mi = 0; mi < MI; mi++)
#pragma unroll
        for (int ni = 0; ni < NI; ni++)
#pragma unroll
            for (int q = 0; q < 4; q++) acc[mi][ni][q] = 0.f;

    auto load_tile = [&](int t, int s) {
#pragma unroll
        for (int i = 0; i < 4; i++) {
            int li = tid + i * 256;
            int m = li >> 3;
            int k4 = (li & 7) << 2;
            int gm = rowBase + m;
            if (gm >= M) gm = M - 1;
            cp_async16(Asm + s * A_STAGE + m * BKP + k4,
                       A + (size_t)gm * K + t * BK + k4);
        }
#pragma unroll
        for (int i = 0; i < (BK * BN) / 1024; i++) {
            int li = tid + i * 256;
            int k = li / (BN / 4);
            int n4 = (li % (BN / 4)) << 2;
            cp_async16(Bsm + s * B_STAGE + k * BNP + n4,
                       B + (size_t)(t * BK + k) * N + colBase + n4);
        }
        cp_commit();
    };

    const int nT = K / BK;
    load_tile(0, 0);
    if (nT > 1) load_tile(1, 1);

    for (int t = 0; t < nT; t++) {
        if (t + 1 < nT) cp_wait1(); else cp_wait0();
        __syncthreads();
        if (t + 2 < nT) load_tile(t + 2, (t + 2) % STAGES);

        const float* Asb = Asm + (t % STAGES) * A_STAGE;
        const float* Bsb = Bsm + (t % STAGES) * B_STAGE;
#pragma unroll
        for (int k8 = 0; k8 < BK / 8; k8++) {
            const int kk = k8 * 8;
            uint32_t a[MI][4], b[NI][2];
#pragma unroll
            for (int mi = 0; mi < MI; mi++) {
                const float* ap = Asb + (warpM * WM + mi * 16 + gq) * BKP + kk + tig;
                if (CVT_A) {
                    a[mi][0] = cvt_tf32(ap[0]);
                    a[mi][1] = cvt_tf32(ap[8 * BKP]);
                    a[mi][2] = cvt_tf32(ap[4]);
                    a[mi][3] = cvt_tf32(ap[8 * BKP + 4]);
                } else {
                    a[mi][0] = __float_as_uint(ap[0]);
                    a[mi][1] = __float_as_uint(ap[8 * BKP]);
                    a[mi][2] = __float_as_uint(ap[4]);
                    a[mi][3] = __float_as_uint(ap[8 * BKP + 4]);
                }
            }
#pragma unroll
            for (int ni = 0; ni < NI; ni++) {
                const float* bp = Bsb + (kk + tig) * BNP + warpN * WN + ni * 8 + gq;
                b[ni][0] = __float_as_uint(bp[0]);
                b[ni][1] = __float_as_uint(bp[4 * BNP]);
            }
#pragma unroll
            for (int mi = 0; mi < MI; mi++)
#pragma unroll
                for (int ni = 0; ni < NI; ni++)
                    mma_tf32(acc[mi][ni], a[mi], b[ni]);
        }
    }

#pragma unroll
    for (int mi = 0; mi < MI; mi++) {
        int row0 = rowBase + warpM * WM + mi * 16 + gq;
#pragma unroll
        for (int ni = 0; ni < NI; ni++) {
            int col = colBase + warpN * WN + ni * 8 + tig * 2;
            float bx = 0.f, by = 0.f;
            if (bias) { bx = bias[col]; by = bias[col + 1]; }
            float2 v;
            v.x = acc[mi][ni][0] + bx;
            v.y = acc[mi][ni][1] + by;
            if (ACT == 1) {
                v.x = v.x > 0.f ? v.x : 0.01f * v.x;
                v.y = v.y > 0.f ? v.y : 0.01f * v.y;
            }
            if (ROUND_OUT) { v.x = round_tf32(v.x); v.y = round_tf32(v.y); }
            if (row0 < M) *(float2*)(C + (size_t)row0 * N + col) = v;
            v.x = acc[mi][ni][2] + bx;
            v.y = acc[mi][ni][3] + by;
            if (ACT == 1) {
                v.x = v.x > 0.f ? v.x : 0.01f * v.x;
                v.y = v.y > 0.f ? v.y : 0.01f * v.y;
            }
            if (ROUND_OUT) { v.x = round_tf32(v.x); v.y = round_tf32(v.y); }
            if (row0 + 8 < M) *(float2*)(C + (size_t)(row0 + 8) * N + col) = v;
        }
    }
}

#define SMEM_BN128 (3 * (128*36 + 32*136) * 4)
#define SMEM_BN64  (3 * (128*36 + 32*72)  * 4)

// ---------------- weight prep: round + concat ----------------
__device__ float cat_src(int i, int K, const float* Wl, const float* Wr)
{
    int tN = K * 512, cN = K * 1024;
    if (i < tN) {
        int k = i >> 9, j = i & 511;
        return (j < 256) ? Wl[(0 * K + k) * 256 + j] : Wr[(1 * K + k) * 256 + (j - 256)];
    }
    i -= tN;
    if (i < cN) {
        int k = i >> 10, j = i & 1023;
        int c = j >> 8, col = j & 255;
        const float* p = (c == 0) ? Wr + (0 * K + k) * 256
                       : (c == 1) ? Wl + (1 * K + k) * 256
                       : (c == 2) ? Wl + (2 * K + k) * 256
                                  : Wr + (3 * K + k) * 256;
        return p[col];
    }
    i -= cN;
    int k = i >> 9, j = i & 511;
    return (j < 256) ? Wr[(2 * K + k) * 256 + j] : Wl[(3 * K + k) * 256 + (j - 256)];
}

__global__ void prep_weights(const float* __restrict__ lw, const float* __restrict__ ow,
                             const float* __restrict__ wl0, const float* __restrict__ wr0,
                             const float* __restrict__ wl1, const float* __restrict__ wr1,
                             float* __restrict__ rlin, float* __restrict__ rout,
                             float* __restrict__ cat0, float* __restrict__ cat1)
{
    int i = blockIdx.x * blockDim.x + threadIdx.x;
    if (i < 49152) { rlin[i] = round_tf32(lw[i]); return; }
    i -= 49152;
    if (i < 196608) { rout[i] = round_tf32(ow[i]); return; }
    i -= 196608;
    if (i < 131072) { cat0[i] = round_tf32(cat_src(i, 64, wl0, wr0)); return; }
    i -= 131072;
    if (i < 524288) cat1[i] = round_tf32(cat_src(i, 256, wl1, wr1));
}

// ---------------- batched edge kernels ----------------
struct EdgeB {
    const int* src[4]; const int* dst[4];
    const float* xl[4]; const float* xr[4];
    int xls[4], xrs[4];
    const float* att;          // conv c at att + c*256
    float* logit[4];
    uint32_t* segm[4]; float* segd[4];
    float* out[4];
    int eStart[5];
};

__global__ void edge_logits_b(EdgeB eb)
{
    int w = blockIdx.x * 8 + (threadIdx.x >> 5);
    if (w >= eb.eStart[4]) return;
    int c = (w >= eb.eStart[2]) ? ((w >= eb.eStart[3]) ? 3 : 2)
                                : ((w >= eb.eStart[1]) ? 1 : 0);
    int e = w - eb.eStart[c];
    int lane = threadIdx.x & 31;
    int s = eb.src[c][e], d = eb.dst[c][e];
    const float4* pl = (const float4*)(eb.xl[c] + (size_t)s * eb.xls[c]) + lane * 2;
    const float4* pr = (const float4*)(eb.xr[c] + (size_t)d * eb.xrs[c]) + lane * 2;
    const float4* pa = (const float4*)(eb.att + c * 256) + lane * 2;
    float sum = 0.f;
#pragma unroll
    for (int i = 0; i < 2; i++) {
        float4 l4 = pl[i], r4 = pr[i], a4 = pa[i];
        float v;
        v = l4.x + r4.x; v = v > 0.f ? v : 0.2f * v; sum += v * a4.x;
        v = l4.y + r4.y; v = v > 0.f ? v : 0.2f * v; sum += v * a4.y;
        v = l4.z + r4.z; v = v > 0.f ? v : 0.2f * v; sum += v * a4.z;
        v = l4.w + r4.w; v = v > 0.f ? v : 0.2f * v; sum += v * a4.w;
    }
    sum += __shfl_xor_sync(0xffffffffu, sum, 1);
    sum += __shfl_xor_sync(0xffffffffu, sum, 2);
    sum += __shfl_xor_sync(0xffffffffu, sum, 4);
    if ((lane & 7) == 0) {
        int h = lane >> 3;
        eb.logit[c][(size_t)e * 4 + h] = sum;
        atomicMax(eb.segm[c] + (size_t)d * 4 + h, fmax_key(sum));
    }
}

__global__ void edge_exp_b(EdgeB eb)
{
    int i = blockIdx.x * blockDim.x + threadIdx.x;
    if (i >= eb.eStart[4]) return;
    int c = (i >= eb.eStart[2]) ? ((i >= eb.eStart[3]) ? 3 : 2)
                                : ((i >= eb.eStart[1]) ? 1 : 0);
    int e = i - eb.eStart[c];
    int d = eb.dst[c][e];
    float4 lg = ((const float4*)eb.logit[c])[e];
    uint4 mk = ((const uint4*)eb.segm[c])[d];
    float4 z;
    z.x = expf(lg.x - fmax_unkey(mk.x));
    z.y = expf(lg.y - fmax_unkey(mk.y));
    z.z = expf(lg.z - fmax_unkey(mk.z));
    z.w = expf(lg.w - fmax_unkey(mk.w));
    ((float4*)eb.logit[c])[e] = z;
    asm volatile("red.global.add.v4.f32 [%0], {%1,%2,%3,%4};"
                 :: "l"(eb.segd[c] + (size_t)d * 4), "f"(z.x), "f"(z.y), "f"(z.z), "f"(z.w)
                 : "memory");
}

__global__ void edge_scatter_b(EdgeB eb)
{
    int w = blockIdx.x * 8 + (threadIdx.x >> 5);
    if (w >= eb.eStart[4]) return;
    int c = (w >= eb.eStart[2]) ? ((w >= eb.eStart[3]) ? 3 : 2)
                                : ((w >= eb.eStart[1]) ? 1 : 0);
    int e = w - eb.eStart[c];
    int lane = threadIdx.x & 31;
    int s = eb.src[c][e], d = eb.dst[c][e];
    int h = lane >> 3;
    float alpha = eb.logit[c][(size_t)e * 4 + h] / eb.segd[c][(size_t)d * 4 + h];
    const float4* pl = (const float4*)(eb.xl[c] + (size_t)s * eb.xls[c]) + lane * 2;
    float* po = eb.out[c] + (size_t)d * FH + lane * 8;
#pragma unroll
    for (int i = 0; i < 2; i++) {
        float4 v = pl[i];
        v.x *= alpha; v.y *= alpha; v.z *= alpha; v.w *= alpha;
        asm volatile("red.global.add.v4.f32 [%0], {%1,%2,%3,%4};"
                     :: "l"(po + i * 4), "f"(v.x), "f"(v.y), "f"(v.z), "f"(v.w)
                     : "memory");
    }
}

// ---------------- batched init: bias broadcast + seg zero ----------------
struct InitB {
    float* out[4]; const float* bias[4];
    float4* seg;
    int o4Start[5]; int tot4;
};

__global__ void conv_init_b(InitB ib)
{
    int i = blockIdx.x * blockDim.x + threadIdx.x;
    if (i < ib.o4Start[4]) {
        int c = (i >= ib.o4Start[2]) ? ((i >= ib.o4Start[3]) ? 3 : 2)
                                     : ((i >= ib.o4Start[1]) ? 1 : 0);
        int local = i - ib.o4Start[c];
        ((float4*)ib.out[c])[local] = ((const float4*)ib.bias[c])[local & 63];
    } else if (i < ib.tot4) {
        ib.seg[i - ib.o4Start[4]] = make_float4(0.f, 0.f, 0.f, 0.f);
    }
}

// ---------------- fused ELU / combine (tf32-rounded outputs) ----------------
__device__ __forceinline__ float eluf(float x) { return x > 0.f ? x : expm1f(x); }

__global__ void elu_comb(const float* __restrict__ ot, const float* __restrict__ oc1,
                         const float* __restrict__ oc2, const float* __restrict__ of,
                         float* __restrict__ ft, float* __restrict__ fc, float* __restrict__ ff)
{
    const int nT4 = NT * 64, nC4 = NC * 64, nF4 = NF * 64;
    int i = blockIdx.x * blockDim.x + threadIdx.x;
    if (i < nT4) {
        float4 v = ((const float4*)ot)[i];
        v.x = round_tf32(eluf(v.x)); v.y = round_tf32(eluf(v.y));
        v.z = round_tf32(eluf(v.z)); v.w = round_tf32(eluf(v.w));
        ((float4*)ft)[i] = v;
    } else if (i < nT4 + nC4) {
        int j = i - nT4;
        float4 x = ((const float4*)oc1)[j];
        float4 y = ((const float4*)oc2)[j];
        float4 v;
        v.x = round_tf32(eluf(0.5f * (x.x + y.x)));
        v.y = round_tf32(eluf(0.5f * (x.y + y.y)));
        v.z = round_tf32(eluf(0.5f * (x.z + y.z)));
        v.w = round_tf32(eluf(0.5f * (x.w + y.w)));
        ((float4*)fc)[j] = v;
    } else if (i < nT4 + nC4 + nF4) {
        int j = i - nT4 - nC4;
        float4 v = ((const float4*)of)[j];
        v.x = round_tf32(eluf(v.x)); v.y = round_tf32(eluf(v.y));
        v.z = round_tf32(eluf(v.z)); v.w = round_tf32(eluf(v.w));
        ((float4*)ff)[j] = v;
    }
}

// ---------------- host orchestration ----------------
extern "C" void kernel_launch(void* const* d_in, const int* in_sizes, int n_in,
                              void* d_out, int out_size)
{
    (void)in_sizes; (void)n_in; (void)out_size;
    const float* x_table  = (const float*)d_in[0];
    const float* x_column = (const float*)d_in[1];
    const float* x_fk     = (const float*)d_in[2];
    const float* lin_w    = (const float*)d_in[3];
    const float* lin_b    = (const float*)d_in[4];
    const float* out_w    = (const float*)d_in[5];
    const float* out_b    = (const float*)d_in[6];
    const float* Wl0      = (const float*)d_in[7];
    const float* Wr0      = (const float*)d_in[8];
    const float* att0     = (const float*)d_in[9];
    const float* b0       = (const float*)d_in[10];
    const float* Wl1      = (const float*)d_in[11];
    const float* Wr1      = (const float*)d_in[12];
    const float* att1     = (const float*)d_in[13];
    const float* b1       = (const float*)d_in[14];
    const int* src_hc = (const int*)d_in[15];
    const int* dst_hc = (const int*)d_in[16];
    const int* src_bt = (const int*)d_in[17];
    const int* dst_bt = (const int*)d_in[18];
    const int* src_is = (const int*)d_in[19];
    const int* dst_is = (const int*)d_in[20];
    const int* src_pt = (const int*)d_in[21];
    const int* dst_pt = (const int*)d_in[22];

    cudaFuncSetAttribute((const void*)gemm_grouped<1, 1, 1, 64, 4, 2>,
                         cudaFuncAttributeMaxDynamicSharedMemorySize, SMEM_BN64);
    cudaFuncSetAttribute((const void*)gemm_grouped<0, 0, 0, 128, 2, 4>,
                         cudaFuncAttributeMaxDynamicSharedMemorySize, SMEM_BN128);

    float* base = nullptr;
    cudaGetSymbolAddress((void**)&base, g_scratch);
    float* feat_t = base + OFF_FEAT_T;
    float* feat_c = base + OFF_FEAT_C;
    float* feat_f = base + OFF_FEAT_F;
    float* xct    = base + OFF_XCT;
    float* xcc    = base + OFF_XCC;
    float* xcf    = base + OFF_XCF;
    float* oc1    = base + OFF_OC1;
    float* ot     = base + OFF_OT;
    float* of     = base + OFF_OF;
    float* oc2    = base + OFF_OC2;
    float* logitB = base + OFF_LOGIT;
    float* segB   = base + OFF_SEG;
    float* rlin   = base + OFF_RLIN;
    float* rout   = base + OFF_ROUT;
    float* cat0   = base + OFF_CAT0;
    float* cat1   = base + OFF_CAT1;

    // 1. weight prep (round + concat): 901120 elements
    prep_weights<<<(901120 + 255) / 256, 256>>>(lin_w, out_w, Wl0, Wr0, Wl1, Wr1,
                                                rlin, rout, cat0, cat1);

    const int bT = (NT + 127) / 128;   // 157
    const int bC = (NC + 127) / 128;   // 1563
    const int bF = (NF + 127) / 128;   // 313

    // 2. input projections: one grouped launch (K=256, N=64, lrelu, rounded)
    {
        GemmGroups gp{};
        gp.K = 256;
        gp.A[0] = x_table;  gp.B[0] = rlin;          gp.bias[0] = lin_b;       gp.C[0] = feat_t; gp.M[0] = NT; gp.N[0] = 64;
        gp.A[1] = x_column; gp.B[1] = rlin + 16384;  gp.bias[1] = lin_b + 64;  gp.C[1] = feat_c; gp.M[1] = NC; gp.N[1] = 64;
        gp.A[2] = x_fk;     gp.B[2] = rlin + 32768;  gp.bias[2] = lin_b + 128; gp.C[2] = feat_f; gp.M[2] = NF; gp.N[2] = 64;
        for (int g = 0; g < 3; g++) { gp.maskX[g] = 0; gp.shiftX[g] = 0; }
        gp.blockStart[0] = 0; gp.blockStart[1] = bT; gp.blockStart[2] = bT + bC;
        int total = bT + bC + bF;
        gemm_grouped<1, 1, 1, 64, 4, 2><<<total, 256, SMEM_BN64>>>(gp);
    }

    // per-conv tables (order: hc, bt, is, pt)
    const int* srcs[4] = {src_hc, src_bt, src_is, src_pt};
    const int* dsts[4] = {dst_hc, dst_bt, dst_is, dst_pt};
    const int  Es[4]   = {E_HC, E_BT, E_IS, E_PT};
    const int  nDs[4]  = {NC, NT, NF, NC};
    float* outs[4]     = {oc1, ot, of, oc2};

    // seg offsets (floats): segm_c then segd_c per conv
    size_t segOffM[4], segOffD[4];
    {
        size_t off = 0;
        for (int c = 0; c < 4; c++) {
            segOffM[c] = off; off += (size_t)nDs[c] * 4;
            segOffD[c] = off; off += (size_t)nDs[c] * 4;
        }
    }
    // logit offsets
    size_t logOff[4]; { size_t off = 0; for (int c = 0; c < 4; c++) { logOff[c] = off; off += (size_t)Es[c] * 4; } }

    for (int l = 0; l < 2; l++) {
        const int Kin = (l == 0) ? 64 : 256;
        float* cat = (l == 0) ? cat0 : cat1;
        const float* att = l ? att1 : att0;
        const float* bb  = l ? b1   : b0;

        // 3. concatenated conv projections: one grouped launch
        {
            GemmGroups gp{};
            gp.K = Kin;
            gp.A[0] = feat_t; gp.B[0] = cat;               gp.bias[0] = nullptr; gp.C[0] = xct; gp.M[0] = NT; gp.N[0] = 512;
            gp.A[1] = feat_c; gp.B[1] = cat + (size_t)Kin * 512;  gp.bias[1] = nullptr; gp.C[1] = xcc; gp.M[1] = NC; gp.N[1] = 1024;
            gp.A[2] = feat_f; gp.B[2] = cat + (size_t)Kin * 1536; gp.bias[2] = nullptr; gp.C[2] = xcf; gp.M[2] = NF; gp.N[2] = 512;
            gp.maskX[0] = 3; gp.shiftX[0] = 2;   // 512/128 = 4 tiles
            gp.maskX[1] = 7; gp.shiftX[1] = 3;   // 1024/128 = 8
            gp.maskX[2] = 3; gp.shiftX[2] = 2;
            gp.blockStart[0] = 0;
            gp.blockStart[1] = bT * 4;
            gp.blockStart[2] = bT * 4 + bC * 8;
            int total = bT * 4 + bC * 8 + bF * 4;
            gemm_grouped<0, 0, 0, 128, 2, 4><<<total, 256, SMEM_BN128>>>(gp);
        }

        // 4. init: bias broadcast into outs + zero seg
        {
            InitB ib{};
            int acc4 = 0;
            for (int c = 0; c < 4; c++) {
                ib.out[c] = outs[c];
                ib.bias[c] = bb + c * 256;
                ib.o4Start[c] = acc4;
                acc4 += nDs[c] * 64;
            }
            ib.o4Start[4] = acc4;
            ib.seg = (float4*)segB;
            ib.tot4 = acc4 + 3680000 / 4;
            conv_init_b<<<(ib.tot4 + 255) / 256, 256>>>(ib);
        }

        // 5. batched edge passes
        EdgeB eb{};
        const float* xls[4] = {xct + 0,   xcc + 256, xcc + 512, xcf + 256};
        const int    lss[4] = {512, 1024, 1024, 512};
        const float* xrs[4] = {xcc + 0,   xct + 256, xcf + 0,   xcc + 768};
        const int    rss[4] = {1024, 512, 512, 1024};
        int eacc = 0;
        for (int c = 0; c < 4; c++) {
            eb.src[c] = srcs[c]; eb.dst[c] = dsts[c];
            eb.xl[c] = xls[c]; eb.xr[c] = xrs[c];
            eb.xls[c] = lss[c]; eb.xrs[c] = rss[c];
            eb.logit[c] = logitB + logOff[c];
            eb.segm[c] = (uint32_t*)(segB + segOffM[c]);
            eb.segd[c] = segB + segOffD[c];
            eb.out[c] = outs[c];
            eb.eStart[c] = eacc;
            eacc += Es[c];
        }
        eb.eStart[4] = eacc;   // 560000
        eb.att = att;

        edge_logits_b<<<(eacc + 7) / 8, 256>>>(eb);
        edge_exp_b<<<(eacc + 255) / 256, 256>>>(eb);
        edge_scatter_b<<<(eacc + 7) / 8, 256>>>(eb);

        // 6. fused ELU / combine
        int tot4 = NT * 64 + NC * 64 + NF * 64;
        elu_comb<<<(tot4 + 255) / 256, 256>>>(ot, oc1, oc2, of, feat_t, feat_c, feat_f);
    }

    // 7. output heads: one grouped launch
    {
        float* out = (float*)d_out;
        GemmGroups gp{};
        gp.K = 256;
        gp.A[0] = feat_t; gp.B[0] = rout;          gp.bias[0] = out_b;       gp.C[0] = out;                        gp.M[0] = NT; gp.N[0] = 256;
        gp.A[1] = feat_c; gp.B[1] = rout + 65536;  gp.bias[1] = out_b + 256; gp.C[1] = out + (size_t)NT * 256;     gp.M[1] = NC; gp.N[1] = 256;
        gp.A[2] = feat_f; gp.B[2] = rout + 131072; gp.bias[2] = out_b + 512; gp.C[2] = out + (size_t)(NT + NC) * 256; gp.M[2] = NF; gp.N[2] = 256;
        for (int g = 0; g < 3; g++) { gp.maskX[g] = 1; gp.shiftX[g] = 1; }  // 2 N-tiles
        gp.blockStart[0] = 0; gp.blockStart[1] = bT * 2; gp.blockStart[2] = bT * 2 + bC * 2;
        int total = (bT + bC + bF) * 2;
        gemm_grouped<0, 0, 0, 128, 2, 4><<<total, 256, SMEM_BN128>>>(gp);
    }
}

// round 8
// speedup vs baseline: 1.2484x; 1.2484x over previous
#include <cuda_runtime.h>
#include <math.h>
#include <stdint.h>

// ---------------- problem constants ----------------
#define NT 20000
#define NC 200000
#define NF 40000
#define E_HC 200000
#define E_BT 200000
#define E_IS 80000
#define E_PT 80000
#define FH 256

// ---------------- scratch offsets (floats) ----------------
// ot | of | oc | seg form ONE contiguous zero-fill region per layer.
static constexpr size_t OFF_FEAT_T = 0;
static constexpr size_t OFF_FEAT_C = OFF_FEAT_T + (size_t)NT * 256;
static constexpr size_t OFF_FEAT_F = OFF_FEAT_C + (size_t)NC * 256;
static constexpr size_t OFF_XCT    = OFF_FEAT_F + (size_t)NF * 256;   // NT x 512
static constexpr size_t OFF_XCC    = OFF_XCT + (size_t)NT * 512;      // NC x 1024
static constexpr size_t OFF_XCF    = OFF_XCC + (size_t)NC * 1024;     // NF x 512
static constexpr size_t OFF_OT     = OFF_XCF + (size_t)NF * 512;      // zero region start
static constexpr size_t OFF_OF     = OFF_OT  + (size_t)NT * 256;
static constexpr size_t OFF_OC     = OFF_OF  + (size_t)NF * 256;      // merged hc+pt accumulator
static constexpr size_t OFF_SEG    = OFF_OC  + (size_t)NC * 256;      // 3,680,000 floats
static constexpr size_t ZERO_FLOATS = (size_t)NT * 256 + (size_t)NF * 256 + (size_t)NC * 256 + 3680000;
static constexpr size_t OFF_LOGIT  = OFF_SEG + 3680000;               // 560000*4
static constexpr size_t OFF_RLIN   = OFF_LOGIT + 2240000;             // 49152
static constexpr size_t OFF_ROUT   = OFF_RLIN + 49152;                // 196608
static constexpr size_t OFF_CAT0   = OFF_ROUT + 196608;               // 64*2048
static constexpr size_t OFF_CAT1   = OFF_CAT0 + 131072;               // 256*2048
static constexpr size_t SCRATCH_TOTAL = OFF_CAT1 + 524288;

__device__ float g_scratch[SCRATCH_TOTAL];

// ---------------- PTX helpers ----------------
__device__ __forceinline__ void cp_async16(void* dst, const void* src)
{
    uint32_t d = (uint32_t)__cvta_generic_to_shared(dst);
    asm volatile("cp.async.cg.shared.global [%0], [%1], 16;\n" :: "r"(d), "l"(src));
}
__device__ __forceinline__ void cp_commit() { asm volatile("cp.async.commit_group;\n" ::: "memory"); }
__device__ __forceinline__ void cp_wait0()  { asm volatile("cp.async.wait_group 0;\n" ::: "memory"); }
__device__ __forceinline__ void cp_wait1()  { asm volatile("cp.async.wait_group 1;\n" ::: "memory"); }

__device__ __forceinline__ uint32_t cvt_tf32(float x)
{
    uint32_t r; asm("cvt.rna.tf32.f32 %0, %1;" : "=r"(r) : "f"(x)); return r;
}
__device__ __forceinline__ float round_tf32(float x) { return __uint_as_float(cvt_tf32(x)); }

__device__ __forceinline__ void mma_tf32(float* c, const uint32_t* a, const uint32_t* b)
{
    asm volatile("mma.sync.aligned.m16n8k8.row.col.f32.tf32.tf32.f32 "
                 "{%0,%1,%2,%3}, {%4,%5,%6,%7}, {%8,%9}, {%0,%1,%2,%3};"
                 : "+f"(c[0]), "+f"(c[1]), "+f"(c[2]), "+f"(c[3])
                 : "r"(a[0]), "r"(a[1]), "r"(a[2]), "r"(a[3]), "r"(b[0]), "r"(b[1]));
}

__device__ __forceinline__ uint32_t fmax_key(float f)
{
    int i = __float_as_int(f);
    return (i >= 0) ? ((uint32_t)i | 0x80000000u) : ~(uint32_t)i;
}
__device__ __forceinline__ float fmax_unkey(uint32_t u)
{
    return (u & 0x80000000u) ? __int_as_float((int)(u & 0x7fffffffu))
                             : __int_as_float((int)~u);
}

// ---------------- grouped tf32 GEMM ----------------
struct GemmGroups {
    const float* A[3]; const float* B[3]; const float* bias[3]; float* C[3];
    int M[3]; int N[3];
    int maskX[3]; int shiftX[3];   // tilesX = maskX+1 (power of 2)
    int blockStart[3];
    int K;
};

template<int CVT_A, int ACT, int ROUND_OUT, int BN, int WARPS_M, int WARPS_N>
__global__ void __launch_bounds__(256, 2)
gemm_grouped(GemmGroups gg)
{
    constexpr int BM = 128, BK = 32;
    constexpr int BKP = 36;
    constexpr int BNP = BN + 8;
    constexpr int WM = BM / WARPS_M, WN = BN / WARPS_N;
    constexpr int MI = WM / 16, NI = WN / 8;
    constexpr int A_STAGE = BM * BKP;
    constexpr int B_STAGE = BK * BNP;
    constexpr int STAGES = 3;

    extern __shared__ float sm[];
    float* Asm = sm;
    float* Bsm = sm + STAGES * A_STAGE;

    const int bid = blockIdx.x;
    const int g = (bid >= gg.blockStart[1]) + (bid >= gg.blockStart[2]);
    const int local = bid - gg.blockStart[g];
    const int tileX = local & gg.maskX[g];
    const int tileY = local >> gg.shiftX[g];

    const float* __restrict__ A = gg.A[g];
    const float* __restrict__ B = gg.B[g];
    const float* __restrict__ bias = gg.bias[g];
    float* __restrict__ C = gg.C[g];
    const int M = gg.M[g], N = gg.N[g], K = gg.K;
    const int rowBase = tileY * BM;
    const int colBase = tileX * BN;

    const int tid  = threadIdx.x;
    const int lane = tid & 31;
    const int warp = tid >> 5;
    const int gq   = lane >> 2;
    const int tig  = lane & 3;
    const int warpM = warp % WARPS_M;
    const int warpN = warp / WARPS_M;

    float acc[MI][NI][4];
#pragma unroll
    for (int mi = 0; mi < MI; mi++)
#pragma unroll
        for (int ni = 0; ni < NI; ni++)
#pragma unroll
            for (int q = 0; q < 4; q++) acc[mi][ni][q] = 0.f;

    auto load_tile = [&](int t, int s) {
#pragma unroll
        for (int i = 0; i < 4; i++) {
            int li = tid + i * 256;
            int m = li >> 3;
            int k4 = (li & 7) << 2;
            int gm = rowBase + m;
            if (gm >= M) gm = M - 1;
            cp_async16(Asm + s * A_STAGE + m * BKP + k4,
                       A + (size_t)gm * K + t * BK + k4);
        }
#pragma unroll
        for (int i = 0; i < (BK * BN) / 1024; i++) {
            int li = tid + i * 256;
            int k = li / (BN / 4);
            int n4 = (li % (BN / 4)) << 2;
            cp_async16(Bsm + s * B_STAGE + k * BNP + n4,
                       B + (size_t)(t * BK + k) * N + colBase + n4);
        }
        cp_commit();
    };

    const int nT = K / BK;
    load_tile(0, 0);
    if (nT > 1) load_tile(1, 1);

    for (int t = 0; t < nT; t++) {
        if (t + 1 < nT) cp_wait1(); else cp_wait0();
        __syncthreads();
        if (t + 2 < nT) load_tile(t + 2, (t + 2) % STAGES);

        const float* Asb = Asm + (t % STAGES) * A_STAGE;
        const float* Bsb = Bsm + (t % STAGES) * B_STAGE;
#pragma unroll
        for (int k8 = 0; k8 < BK / 8; k8++) {
            const int kk = k8 * 8;
            uint32_t a[MI][4], b[NI][2];
#pragma unroll
            for (int mi = 0; mi < MI; mi++) {
                const float* ap = Asb + (warpM * WM + mi * 16 + gq) * BKP + kk + tig;
                if (CVT_A) {
                    a[mi][0] = cvt_tf32(ap[0]);
                    a[mi][1] = cvt_tf32(ap[8 * BKP]);
                    a[mi][2] = cvt_tf32(ap[4]);
                    a[mi][3] = cvt_tf32(ap[8 * BKP + 4]);
                } else {
                    a[mi][0] = __float_as_uint(ap[0]);
                    a[mi][1] = __float_as_uint(ap[8 * BKP]);
                    a[mi][2] = __float_as_uint(ap[4]);
                    a[mi][3] = __float_as_uint(ap[8 * BKP + 4]);
                }
            }
#pragma unroll
            for (int ni = 0; ni < NI; ni++) {
                const float* bp = Bsb + (kk + tig) * BNP + warpN * WN + ni * 8 + gq;
                b[ni][0] = __float_as_uint(bp[0]);
                b[ni][1] = __float_as_uint(bp[4 * BNP]);
            }
#pragma unroll
            for (int mi = 0; mi < MI; mi++)
#pragma unroll
                for (int ni = 0; ni < NI; ni++)
                    mma_tf32(acc[mi][ni], a[mi], b[ni]);
        }
    }

#pragma unroll
    for (int mi = 0; mi < MI; mi++) {
        int row0 = rowBase + warpM * WM + mi * 16 + gq;
#pragma unroll
        for (int ni = 0; ni < NI; ni++) {
            int col = colBase + warpN * WN + ni * 8 + tig * 2;
            float bx = 0.f, by = 0.f;
            if (bias) { bx = bias[col]; by = bias[col + 1]; }
            float2 v;
            v.x = acc[mi][ni][0] + bx;
            v.y = acc[mi][ni][1] + by;
            if (ACT == 1) {
                v.x = v.x > 0.f ? v.x : 0.01f * v.x;
                v.y = v.y > 0.f ? v.y : 0.01f * v.y;
            }
            if (ROUND_OUT) { v.x = round_tf32(v.x); v.y = round_tf32(v.y); }
            if (row0 < M) *(float2*)(C + (size_t)row0 * N + col) = v;
            v.x = acc[mi][ni][2] + bx;
            v.y = acc[mi][ni][3] + by;
            if (ACT == 1) {
                v.x = v.x > 0.f ? v.x : 0.01f * v.x;
                v.y = v.y > 0.f ? v.y : 0.01f * v.y;
            }
            if (ROUND_OUT) { v.x = round_tf32(v.x); v.y = round_tf32(v.y); }
            if (row0 + 8 < M) *(float2*)(C + (size_t)(row0 + 8) * N + col) = v;
        }
    }
}

#define SMEM_BN128 (3 * (128*36 + 32*136) * 4)
#define SMEM_BN64  (3 * (128*36 + 32*72)  * 4)

// ---------------- weight prep: round + concat ----------------
__device__ float cat_src(int i, int K, const float* Wl, const float* Wr)
{
    int tN = K * 512, cN = K * 1024;
    if (i < tN) {
        int k = i >> 9, j = i & 511;
        return (j < 256) ? Wl[(0 * K + k) * 256 + j] : Wr[(1 * K + k) * 256 + (j - 256)];
    }
    i -= tN;
    if (i < cN) {
        int k = i >> 10, j = i & 1023;
        int c = j >> 8, col = j & 255;
        const float* p = (c == 0) ? Wr + (0 * K + k) * 256
                       : (c == 1) ? Wl + (1 * K + k) * 256
                       : (c == 2) ? Wl + (2 * K + k) * 256
                                  : Wr + (3 * K + k) * 256;
        return p[col];
    }
    i -= cN;
    int k = i >> 9, j = i & 511;
    return (j < 256) ? Wr[(2 * K + k) * 256 + j] : Wl[(3 * K + k) * 256 + (j - 256)];
}

__global__ void prep_weights(const float* __restrict__ lw, const float* __restrict__ ow,
                             const float* __restrict__ wl0, const float* __restrict__ wr0,
                             const float* __restrict__ wl1, const float* __restrict__ wr1,
                             float* __restrict__ rlin, float* __restrict__ rout,
                             float* __restrict__ cat0, float* __restrict__ cat1)
{
    int i = blockIdx.x * blockDim.x + threadIdx.x;
    if (i < 49152) { rlin[i] = round_tf32(lw[i]); return; }
    i -= 49152;
    if (i < 196608) { rout[i] = round_tf32(ow[i]); return; }
    i -= 196608;
    if (i < 131072) { cat0[i] = round_tf32(cat_src(i, 64, wl0, wr0)); return; }
    i -= 131072;
    if (i < 524288) cat1[i] = round_tf32(cat_src(i, 256, wl1, wr1));
}

// ---------------- batched edge kernels ----------------
struct EdgeB {
    const int* src[4]; const int* dst[4];
    const float* xl[4]; const float* xr[4];
    int xls[4], xrs[4];
    const float* att;
    float* logit[4];
    uint32_t* segm[4]; float* segd[4];
    float* out[4];
    int eStart[5];
};

__global__ void edge_logits_b(EdgeB eb)
{
    int w = blockIdx.x * 8 + (threadIdx.x >> 5);
    if (w >= eb.eStart[4]) return;
    int c = (w >= eb.eStart[2]) ? ((w >= eb.eStart[3]) ? 3 : 2)
                                : ((w >= eb.eStart[1]) ? 1 : 0);
    int e = w - eb.eStart[c];
    int lane = threadIdx.x & 31;
    int s = eb.src[c][e], d = eb.dst[c][e];
    const float4* pl = (const float4*)(eb.xl[c] + (size_t)s * eb.xls[c]) + lane * 2;
    const float4* pr = (const float4*)(eb.xr[c] + (size_t)d * eb.xrs[c]) + lane * 2;
    const float4* pa = (const float4*)(eb.att + c * 256) + lane * 2;
    float sum = 0.f;
#pragma unroll
    for (int i = 0; i < 2; i++) {
        float4 l4 = pl[i], r4 = pr[i], a4 = pa[i];
        float v;
        v = l4.x + r4.x; v = v > 0.f ? v : 0.2f * v; sum += v * a4.x;
        v = l4.y + r4.y; v = v > 0.f ? v : 0.2f * v; sum += v * a4.y;
        v = l4.z + r4.z; v = v > 0.f ? v : 0.2f * v; sum += v * a4.z;
        v = l4.w + r4.w; v = v > 0.f ? v : 0.2f * v; sum += v * a4.w;
    }
    sum += __shfl_xor_sync(0xffffffffu, sum, 1);
    sum += __shfl_xor_sync(0xffffffffu, sum, 2);
    sum += __shfl_xor_sync(0xffffffffu, sum, 4);
    if ((lane & 7) == 0) {
        int h = lane >> 3;
        eb.logit[c][(size_t)e * 4 + h] = sum;
        atomicMax(eb.segm[c] + (size_t)d * 4 + h, fmax_key(sum));
    }
}

__global__ void edge_exp_b(EdgeB eb)
{
    int i = blockIdx.x * blockDim.x + threadIdx.x;
    if (i >= eb.eStart[4]) return;
    int c = (i >= eb.eStart[2]) ? ((i >= eb.eStart[3]) ? 3 : 2)
                                : ((i >= eb.eStart[1]) ? 1 : 0);
    int e = i - eb.eStart[c];
    int d = eb.dst[c][e];
    float4 lg = ((const float4*)eb.logit[c])[e];
    uint4 mk = ((const uint4*)eb.segm[c])[d];
    float4 z;
    z.x = expf(lg.x - fmax_unkey(mk.x));
    z.y = expf(lg.y - fmax_unkey(mk.y));
    z.z = expf(lg.z - fmax_unkey(mk.z));
    z.w = expf(lg.w - fmax_unkey(mk.w));
    ((float4*)eb.logit[c])[e] = z;
    asm volatile("red.global.add.v4.f32 [%0], {%1,%2,%3,%4};"
                 :: "l"(eb.segd[c] + (size_t)d * 4), "f"(z.x), "f"(z.y), "f"(z.z), "f"(z.w)
                 : "memory");
}

__global__ void edge_scatter_b(EdgeB eb)
{
    int w = blockIdx.x * 8 + (threadIdx.x >> 5);
    if (w >= eb.eStart[4]) return;
    int c = (w >= eb.eStart[2]) ? ((w >= eb.eStart[3]) ? 3 : 2)
                                : ((w >= eb.eStart[1]) ? 1 : 0);
    int e = w - eb.eStart[c];
    int lane = threadIdx.x & 31;
    int s = eb.src[c][e], d = eb.dst[c][e];
    int h = lane >> 3;
    float alpha = eb.logit[c][(size_t)e * 4 + h] / eb.segd[c][(size_t)d * 4 + h];
    const float4* pl = (const float4*)(eb.xl[c] + (size_t)s * eb.xls[c]) + lane * 2;
    float* po = eb.out[c] + (size_t)d * FH + lane * 8;
#pragma unroll
    for (int i = 0; i < 2; i++) {
        float4 v = pl[i];
        v.x *= alpha; v.y *= alpha; v.z *= alpha; v.w *= alpha;
        asm volatile("red.global.add.v4.f32 [%0], {%1,%2,%3,%4};"
                     :: "l"(po + i * 4), "f"(v.x), "f"(v.y), "f"(v.z), "f"(v.w)
                     : "memory");
    }
}

// ---------------- fused ELU / combine with bias (tf32-rounded outputs) -----
__device__ __forceinline__ float eluf(float x) { return x > 0.f ? x : expm1f(x); }

__global__ void elu_comb(const float* __restrict__ ot, const float* __restrict__ oc,
                         const float* __restrict__ of,
                         const float* __restrict__ b_hc, const float* __restrict__ b_bt,
                         const float* __restrict__ b_is, const float* __restrict__ b_pt,
                         float* __restrict__ ft, float* __restrict__ fc, float* __restrict__ ff)
{
    const int nT4 = NT * 64, nC4 = NC * 64, nF4 = NF * 64;
    int i = blockIdx.x * blockDim.x + threadIdx.x;
    if (i < nT4) {
        float4 v = ((const float4*)ot)[i];
        float4 b = ((const float4*)b_bt)[i & 63];
        v.x = round_tf32(eluf(v.x + b.x)); v.y = round_tf32(eluf(v.y + b.y));
        v.z = round_tf32(eluf(v.z + b.z)); v.w = round_tf32(eluf(v.w + b.w));
        ((float4*)ft)[i] = v;
    } else if (i < nT4 + nC4) {
        int j = i - nT4;
        float4 x = ((const float4*)oc)[j];
        float4 bh = ((const float4*)b_hc)[j & 63];
        float4 bp = ((const float4*)b_pt)[j & 63];
        float4 v;
        v.x = round_tf32(eluf(0.5f * (x.x + bh.x + bp.x)));
        v.y = round_tf32(eluf(0.5f * (x.y + bh.y + bp.y)));
        v.z = round_tf32(eluf(0.5f * (x.z + bh.z + bp.z)));
        v.w = round_tf32(eluf(0.5f * (x.w + bh.w + bp.w)));
        ((float4*)fc)[j] = v;
    } else if (i < nT4 + nC4 + nF4) {
        int j = i - nT4 - nC4;
        float4 v = ((const float4*)of)[j];
        float4 b = ((const float4*)b_is)[j & 63];
        v.x = round_tf32(eluf(v.x + b.x)); v.y = round_tf32(eluf(v.y + b.y));
        v.z = round_tf32(eluf(v.z + b.z)); v.w = round_tf32(eluf(v.w + b.w));
        ((float4*)ff)[j] = v;
    }
}

// ---------------- host orchestration ----------------
extern "C" void kernel_launch(void* const* d_in, const int* in_sizes, int n_in,
                              void* d_out, int out_size)
{
    (void)in_sizes; (void)n_in; (void)out_size;
    const float* x_table  = (const float*)d_in[0];
    const float* x_column = (const float*)d_in[1];
    const float* x_fk     = (const float*)d_in[2];
    const float* lin_w    = (const float*)d_in[3];
    const float* lin_b    = (const float*)d_in[4];
    const float* out_w    = (const float*)d_in[5];
    const float* out_b    = (const float*)d_in[6];
    const float* Wl0      = (const float*)d_in[7];
    const float* Wr0      = (const float*)d_in[8];
    const float* att0     = (const float*)d_in[9];
    const float* b0       = (const float*)d_in[10];
    const float* Wl1      = (const float*)d_in[11];
    const float* Wr1      = (const float*)d_in[12];
    const float* att1     = (const float*)d_in[13];
    const float* b1       = (const float*)d_in[14];
    const int* src_hc = (const int*)d_in[15];
    const int* dst_hc = (const int*)d_in[16];
    const int* src_bt = (const int*)d_in[17];
    const int* dst_bt = (const int*)d_in[18];
    const int* src_is = (const int*)d_in[19];
    const int* dst_is = (const int*)d_in[20];
    const int* src_pt = (const int*)d_in[21];
    const int* dst_pt = (const int*)d_in[22];

    cudaFuncSetAttribute((const void*)gemm_grouped<1, 1, 1, 64, 4, 2>,
                         cudaFuncAttributeMaxDynamicSharedMemorySize, SMEM_BN64);
    cudaFuncSetAttribute((const void*)gemm_grouped<0, 0, 0, 128, 2, 4>,
                         cudaFuncAttributeMaxDynamicSharedMemorySize, SMEM_BN128);

    float* base = nullptr;
    cudaGetSymbolAddress((void**)&base, g_scratch);
    float* feat_t = base + OFF_FEAT_T;
    float* feat_c = base + OFF_FEAT_C;
    float* feat_f = base + OFF_FEAT_F;
    float* xct    = base + OFF_XCT;
    float* xcc    = base + OFF_XCC;
    float* xcf    = base + OFF_XCF;
    float* ot     = base + OFF_OT;
    float* of     = base + OFF_OF;
    float* oc     = base + OFF_OC;
    float* segB   = base + OFF_SEG;
    float* logitB = base + OFF_LOGIT;
    float* rlin   = base + OFF_RLIN;
    float* rout   = base + OFF_ROUT;
    float* cat0   = base + OFF_CAT0;
    float* cat1   = base + OFF_CAT1;

    // 1. weight prep (round + concat)
    prep_weights<<<(901120 + 255) / 256, 256>>>(lin_w, out_w, Wl0, Wr0, Wl1, Wr1,
                                                rlin, rout, cat0, cat1);

    const int bT = (NT + 127) / 128;   // 157
    const int bC = (NC + 127) / 128;   // 1563
    const int bF = (NF + 127) / 128;   // 313

    // 2. input projections: one grouped launch
    {
        GemmGroups gp{};
        gp.K = 256;
        gp.A[0] = x_table;  gp.B[0] = rlin;          gp.bias[0] = lin_b;       gp.C[0] = feat_t; gp.M[0] = NT; gp.N[0] = 64;
        gp.A[1] = x_column; gp.B[1] = rlin + 16384;  gp.bias[1] = lin_b + 64;  gp.C[1] = feat_c; gp.M[1] = NC; gp.N[1] = 64;
        gp.A[2] = x_fk;     gp.B[2] = rlin + 32768;  gp.bias[2] = lin_b + 128; gp.C[2] = feat_f; gp.M[2] = NF; gp.N[2] = 64;
        for (int g = 0; g < 3; g++) { gp.maskX[g] = 0; gp.shiftX[g] = 0; }
        gp.blockStart[0] = 0; gp.blockStart[1] = bT; gp.blockStart[2] = bT + bC;
        gemm_grouped<1, 1, 1, 64, 4, 2><<<bT + bC + bF, 256, SMEM_BN64>>>(gp);
    }

    // per-conv tables (order: hc, bt, is, pt)
    const int* srcs[4] = {src_hc, src_bt, src_is, src_pt};
    const int* dsts[4] = {dst_hc, dst_bt, dst_is, dst_pt};
    const int  Es[4]   = {E_HC, E_BT, E_IS, E_PT};
    const int  nDs[4]  = {NC, NT, NF, NC};
    float* outs[4]     = {oc, ot, of, oc};   // hc and pt share the merged accumulator

    size_t segOffM[4], segOffD[4];
    {
        size_t off = 0;
        for (int c = 0; c < 4; c++) {
            segOffM[c] = off; off += (size_t)nDs[c] * 4;
            segOffD[c] = off; off += (size_t)nDs[c] * 4;
        }
    }
    size_t logOff[4]; { size_t off = 0; for (int c = 0; c < 4; c++) { logOff[c] = off; off += (size_t)Es[c] * 4; } }

    for (int l = 0; l < 2; l++) {
        const int Kin = (l == 0) ? 64 : 256;
        float* cat = (l == 0) ? cat0 : cat1;
        const float* att = l ? att1 : att0;
        const float* bb  = l ? b1   : b0;

        // 3. concatenated conv projections: one grouped launch
        {
            GemmGroups gp{};
            gp.K = Kin;
            gp.A[0] = feat_t; gp.B[0] = cat;                      gp.bias[0] = nullptr; gp.C[0] = xct; gp.M[0] = NT; gp.N[0] = 512;
            gp.A[1] = feat_c; gp.B[1] = cat + (size_t)Kin * 512;  gp.bias[1] = nullptr; gp.C[1] = xcc; gp.M[1] = NC; gp.N[1] = 1024;
            gp.A[2] = feat_f; gp.B[2] = cat + (size_t)Kin * 1536; gp.bias[2] = nullptr; gp.C[2] = xcf; gp.M[2] = NF; gp.N[2] = 512;
            gp.maskX[0] = 3; gp.shiftX[0] = 2;
            gp.maskX[1] = 7; gp.shiftX[1] = 3;
            gp.maskX[2] = 3; gp.shiftX[2] = 2;
            gp.blockStart[0] = 0;
            gp.blockStart[1] = bT * 4;
            gp.blockStart[2] = bT * 4 + bC * 8;
            gemm_grouped<0, 0, 0, 128, 2, 4><<<bT * 4 + bC * 8 + bF * 4, 256, SMEM_BN128>>>(gp);
        }

        // 4. zero the whole accumulator region (ot|of|oc|seg) in one memset
        cudaMemsetAsync(ot, 0, ZERO_FLOATS * sizeof(float), 0);

        // 5. batched edge passes
        EdgeB eb{};
        const float* xls[4] = {xct + 0,   xcc + 256, xcc + 512, xcf + 256};
        const int    lss[4] = {512, 1024, 1024, 512};
        const float* xrs[4] = {xcc + 0,   xct + 256, xcf + 0,   xcc + 768};
        const int    rss[4] = {1024, 512, 512, 1024};
        int eacc = 0;
        for (int c = 0; c < 4; c++) {
            eb.src[c] = srcs[c]; eb.dst[c] = dsts[c];
            eb.xl[c] = xls[c]; eb.xr[c] = xrs[c];
            eb.xls[c] = lss[c]; eb.xrs[c] = rss[c];
            eb.logit[c] = logitB + logOff[c];
            eb.segm[c] = (uint32_t*)(segB + segOffM[c]);
            eb.segd[c] = segB + segOffD[c];
            eb.out[c] = outs[c];
            eb.eStart[c] = eacc;
            eacc += Es[c];
        }
        eb.eStart[4] = eacc;
        eb.att = att;

        edge_logits_b<<<(eacc + 7) / 8, 256>>>(eb);
        edge_exp_b<<<(eacc + 255) / 256, 256>>>(eb);
        edge_scatter_b<<<(eacc + 7) / 8, 256>>>(eb);

        // 6. fused ELU / combine with bias fold-in
        int tot4 = NT * 64 + NC * 64 + NF * 64;
        elu_comb<<<(tot4 + 255) / 256, 256>>>(ot, oc, of,
                                              bb + 0, bb + 256, bb + 512, bb + 768,
                                              feat_t, feat_c, feat_f);
    }

    // 7. output heads: one grouped launch
    {
        float* out = (float*)d_out;
        GemmGroups gp{};
        gp.K = 256;
        gp.A[0] = feat_t; gp.B[0] = rout;          gp.bias[0] = out_b;       gp.C[0] = out;                           gp.M[0] = NT; gp.N[0] = 256;
        gp.A[1] = feat_c; gp.B[1] = rout + 65536;  gp.bias[1] = out_b + 256; gp.C[1] = out + (size_t)NT * 256;        gp.M[1] = NC; gp.N[1] = 256;
        gp.A[2] = feat_f; gp.B[2] = rout + 131072; gp.bias[2] = out_b + 512; gp.C[2] = out + (size_t)(NT + NC) * 256; gp.M[2] = NF; gp.N[2] = 256;
        for (int g = 0; g < 3; g++) { gp.maskX[g] = 1; gp.shiftX[g] = 1; }
        gp.blockStart[0] = 0; gp.blockStart[1] = bT * 2; gp.blockStart[2] = bT * 2 + bC * 2;
        gemm_grouped<0, 0, 0, 128, 2, 4><<<(bT + bC + bF) * 2, 256, SMEM_BN128>>>(gp);
    }
}